// round 4
// baseline (speedup 1.0000x reference)
#include <cuda_runtime.h>

#define NCL 127            // active clusters (last cluster excluded by reference)
#define NPTS 1024
#define THREADS 128        // 4 warps per CTA
#define RPT 4              // rows per thread -> 128 rows per warp, 512 per CTA
#define BIGF 3.4e38f

// Per-(cluster,half) row-term partials; per-(half,cluster) column-min partials;
// per-cluster totals.
__device__ float g_rowsum[2 * NCL];
__device__ float g_col[2 * NCL * NPTS];   // [half][c][j]
__device__ float g_cl[NCL];

// One CTA per (cluster c in [0,126], half in {0,1}); CTA covers rows
// [half*512, half*512+512) x all 1024 cols of cluster c's distance matrix
//   d(i,j) = |a_i|^2 + |b_j|^2 - 2 a_i.b_j
// Row-min (over j) and col-min (over i) extracted in ONE pass:
//   t = |b_j|^2 - 2 a.b   (3 FFMA)  -> rowmin accumulator (add |a_i|^2 at end)
//   u = t + |a_i|^2 = d   (1 FADD)  -> colmin
// Col-min across the 32 lanes uses a register "carry" passed lane-to-lane with
// __shfl_down each iteration under lane rotation jc = (j+lane) & 1023:
// column j's full min arrives at lane 0 at iteration j (mod 1024); the final
// 32 extra iterations re-complete columns 0..31 (idempotent overwrite).
__global__ void __launch_bounds__(THREADS, 2)
chamfer_main(const float* __restrict__ in_pts,
             const float* __restrict__ out_pts) {
    const int c    = blockIdx.x >> 1;
    const int half = blockIdx.x & 1;

    const float* ap = in_pts  + (size_t)c * NPTS * 3;   // rows
    const float* bp = out_pts + (size_t)c * NPTS * 3;   // cols

    __shared__ float4 sb[NPTS];        // (x,y,z,|b|^2) per column point, 16KB
    __shared__ float  wcol[4][NPTS];   // per-warp colmin partials, 16KB
    __shared__ float  rbuf[4];

    const int tid  = threadIdx.x;
    const int wid  = tid >> 5;
    const int lane = tid & 31;

    for (int j = tid; j < NPTS; j += THREADS) {
        float x = bp[3 * j + 0];
        float y = bp[3 * j + 1];
        float z = bp[3 * j + 2];
        sb[j] = make_float4(x, y, z, fmaf(x, x, fmaf(y, y, z * z)));
    }
    __syncthreads();

    // This warp's rows.
    float a2x[RPT], a2y[RPT], a2z[RPT], an[RPT], m[RPT];
#pragma unroll
    for (int r = 0; r < RPT; r++) {
        int row = half * 512 + wid * 128 + r * 32 + lane;
        float x = ap[3 * row + 0];
        float y = ap[3 * row + 1];
        float z = ap[3 * row + 2];
        a2x[r] = -2.0f * x;
        a2y[r] = -2.0f * y;
        a2z[r] = -2.0f * z;
        an[r]  = fmaf(x, x, fmaf(y, y, z * z));
        m[r]   = BIGF;
    }

    float cm = BIGF;           // traveling column-min carry
    float* mycol = wcol[wid];

#pragma unroll 4
    for (int j = 0; j < NPTS + 32; j++) {
        float4 b = sb[(j + lane) & (NPTS - 1)];
        float t0 = fmaf(a2x[0], b.x, fmaf(a2y[0], b.y, fmaf(a2z[0], b.z, b.w)));
        float t1 = fmaf(a2x[1], b.x, fmaf(a2y[1], b.y, fmaf(a2z[1], b.z, b.w)));
        float t2 = fmaf(a2x[2], b.x, fmaf(a2y[2], b.y, fmaf(a2z[2], b.z, b.w)));
        float t3 = fmaf(a2x[3], b.x, fmaf(a2y[3], b.y, fmaf(a2z[3], b.z, b.w)));
        m[0] = fminf(m[0], t0);
        m[1] = fminf(m[1], t1);
        m[2] = fminf(m[2], t2);
        m[3] = fminf(m[3], t3);
        float u0 = t0 + an[0];
        float u1 = t1 + an[1];
        float u2 = t2 + an[2];
        float u3 = t3 + an[3];
        float umin = fminf(fminf(u0, u1), fminf(u2, u3));
        cm = __shfl_down_sync(0xffffffffu, cm, 1);
        cm = (lane == 31) ? BIGF : cm;
        cm = fminf(cm, umin);
        if (lane == 0) mycol[j & (NPTS - 1)] = cm;
    }

    // Row-term partial: sum over this thread's rows of (|a|^2 + min_j t).
    float s = 0.0f;
#pragma unroll
    for (int r = 0; r < RPT; r++) s += m[r] + an[r];
#pragma unroll
    for (int off = 16; off > 0; off >>= 1)
        s += __shfl_down_sync(0xffffffffu, s, off);
    if (lane == 0) rbuf[wid] = s;
    __syncthreads();
    if (tid == 0)
        g_rowsum[blockIdx.x] = (rbuf[0] + rbuf[1]) + (rbuf[2] + rbuf[3]);

    // Column-min partial over this CTA's 512 rows: min of the 4 warp arrays.
    for (int idx = tid; idx < NPTS; idx += THREADS) {
        float v = fminf(fminf(wcol[0][idx], wcol[1][idx]),
                        fminf(wcol[2][idx], wcol[3][idx]));
        g_col[((size_t)half * NCL + c) * NPTS + idx] = v;
    }
}

// Per-cluster reduce: merge the two half colmin partials, add row partials.
__global__ void cluster_reduce_kernel() {
    const int c   = blockIdx.x;      // 0..126
    const int tid = threadIdx.x;     // 256
    const float* c0 = g_col + (size_t)c * NPTS;
    const float* c1 = g_col + (size_t)(NCL + c) * NPTS;

    float s = 0.0f;
    for (int j = tid; j < NPTS; j += 256)
        s += fminf(c0[j], c1[j]);

#pragma unroll
    for (int off = 16; off > 0; off >>= 1)
        s += __shfl_down_sync(0xffffffffu, s, off);
    __shared__ float ws[8];
    if ((tid & 31) == 0) ws[tid >> 5] = s;
    __syncthreads();
    if (tid < 8) {
        s = ws[tid];
#pragma unroll
        for (int off = 4; off > 0; off >>= 1)
            s += __shfl_down_sync(0xffu, s, off);
        if (tid == 0)
            g_cl[c] = s + g_rowsum[2 * c] + g_rowsum[2 * c + 1];
    }
}

__global__ void final_sum_kernel(float* __restrict__ out) {
    const int tid = threadIdx.x;     // 128
    float s = (tid < NCL) ? g_cl[tid] : 0.0f;
#pragma unroll
    for (int off = 16; off > 0; off >>= 1)
        s += __shfl_down_sync(0xffffffffu, s, off);
    __shared__ float ws[4];
    if ((tid & 31) == 0) ws[tid >> 5] = s;
    __syncthreads();
    if (tid == 0) out[0] = (ws[0] + ws[1]) + (ws[2] + ws[3]);
}

extern "C" void kernel_launch(void* const* d_in, const int* in_sizes, int n_in,
                              void* d_out, int out_size) {
    const float* in_pts  = (const float*)d_in[0];
    const float* out_pts = (const float*)d_in[2];
    float* out = (float*)d_out;

    chamfer_main<<<2 * NCL, THREADS>>>(in_pts, out_pts);
    cluster_reduce_kernel<<<NCL, 256>>>();
    final_sum_kernel<<<1, 128>>>(out);
}